// round 15
// baseline (speedup 1.0000x reference)
#include <cuda_runtime.h>
#include <cstdint>
#include <float.h>

#define N_NODES 100000
#define N_EDGES 1200000
#define IN_F 128
#define HID 64
#define OUT_F 40

// ---------------- device scratch (no allocations allowed) ----------------
__device__ int   g_deg[N_NODES];          // in-degree incl. self-loop
__device__ int   g_edge[2 * N_EDGES];     // int32 [src | dst]
__device__ int   g_is64;
__device__ float g_hs[(size_t)N_NODES * HID];    // dinv-prescaled transformed feats
__device__ float g_h1[(size_t)N_NODES * HID];    // layer-1 accumulator/activations

// -------- init: deg=1 (self-loop) + detect edge dtype --------
__global__ void k_init(const long long* __restrict__ ei, int n) {
    int i = blockIdx.x * blockDim.x + threadIdx.x;
    if (i < n) g_deg[i] = 1;
    if (i == 0) {
        int ok = 1;
        #pragma unroll
        for (int j = 0; j < 16; j++) {
            long long v = ei[j];
            if (v < 0 || v >= n) ok = 0;
        }
        g_is64 = ok;
    }
}

// convert to int32 + count in-degree of dst half in one pass
__global__ void k_convert(const void* __restrict__ ei, int e) {
    int i = blockIdx.x * blockDim.x + threadIdx.x;
    if (i < 2 * e) {
        int v = g_is64 ? (int)((const long long*)ei)[i]
                       : ((const int*)ei)[i];
        g_edge[i] = v;
        if (i >= e) atomicAdd(&g_deg[v], 1);
    }
}

// --- dense GEMM: hs[n,64] = (A[n,K] @ W[K,64]) * dinv[row]  (prescaled),
//     dual-write: also initializes the scatter accumulator to the same value
//     (self-loop term). dinv inline from g_deg.
template <int K>
__global__ void k_gemm_hs(const float* __restrict__ A, const float* __restrict__ W,
                          float* __restrict__ accum, int n) {
    __shared__ __align__(16) float sW[64 * 64];
    __shared__ float sA[64 * 65];

    const int t = threadIdx.x;           // 256 threads
    const int row0 = blockIdx.x * 64;
    const int ty = t >> 4, tx = t & 15;  // 16x16 thread tile
    const int r0 = ty * 4, c0 = tx * 4;

    float acc[4][4] = {};

    for (int k0 = 0; k0 < K; k0 += 64) {
        __syncthreads();
        for (int i = t; i < 64 * 64 / 4; i += 256)
            ((float4*)sW)[i] = ((const float4*)(W + (size_t)k0 * 64))[i];
        for (int i = t; i < 64 * 16; i += 256) {
            int r = i >> 4;
            int kc = (i & 15) * 4;
            float4 v = make_float4(0.f, 0.f, 0.f, 0.f);
            if (row0 + r < n)
                v = *(const float4*)(A + (size_t)(row0 + r) * K + k0 + kc);
            float* d = &sA[r * 65 + kc];
            d[0] = v.x; d[1] = v.y; d[2] = v.z; d[3] = v.w;
        }
        __syncthreads();

        #pragma unroll 8
        for (int kk = 0; kk < 64; kk++) {
            float4 w4 = *(float4*)&sW[kk * 64 + c0];
            #pragma unroll
            for (int j = 0; j < 4; j++) {
                float a = sA[(r0 + j) * 65 + kk];
                acc[j][0] += a * w4.x;
                acc[j][1] += a * w4.y;
                acc[j][2] += a * w4.z;
                acc[j][3] += a * w4.w;
            }
        }
    }

    #pragma unroll
    for (int j = 0; j < 4; j++) {
        int r = row0 + r0 + j;
        if (r < n) {
            float dv = rsqrtf((float)g_deg[r]);
            float4 v = make_float4(acc[j][0] * dv, acc[j][1] * dv,
                                   acc[j][2] * dv, acc[j][3] * dv);
            *(float4*)&g_hs[(size_t)r * 64 + c0] = v;
            *(float4*)&accum[(size_t)r * 64 + c0] = v;   // self-loop init
        }
    }
}

// edge-parallel scatter: 16 threads per edge; each thread gathers a float4
// slice of hs[src] and red.adds it into accum[dst]. Warp covers 2 edges ->
// one LDG.128 instruction per 2 rows; massive thread-level parallelism,
// no per-warp edge chains.
__global__ void k_scatter(float* __restrict__ accum, int e) {
    int i = blockIdx.x * blockDim.x + threadIdx.x;
    if (i < e * 16) {
        int edge = i >> 4;
        int sl = i & 15;
        int s = g_edge[edge];
        int d = g_edge[e + edge];
        float4 v = *(const float4*)(g_hs + (size_t)s * 64 + 4 * sl);
        float* p = accum + (size_t)d * 64 + 4 * sl;
        asm volatile("red.global.add.v4.f32 [%0], {%1,%2,%3,%4};"
                     :: "l"(p), "f"(v.x), "f"(v.y), "f"(v.z), "f"(v.w)
                     : "memory");
    }
}

// finish: h = act(acc * dinv + b)
__global__ void k_bias_act(float* __restrict__ h, const float* __restrict__ b,
                           int n, int do_relu) {
    int i = blockIdx.x * blockDim.x + threadIdx.x;
    if (i < n * 16) {
        int node = i >> 4;
        int sl = i & 15;
        float dv = rsqrtf((float)g_deg[node]);
        float4 v = *(const float4*)(h + (size_t)node * 64 + 4 * sl);
        float4 bb = *(const float4*)(b + 4 * sl);
        float vx = v.x * dv + bb.x;
        float vy = v.y * dv + bb.y;
        float vz = v.z * dv + bb.z;
        float vw = v.w * dv + bb.w;
        if (do_relu) {
            vx = fmaxf(vx, 0.f); vy = fmaxf(vy, 0.f);
            vz = fmaxf(vz, 0.f); vw = fmaxf(vw, 0.f);
        }
        *(float4*)(h + (size_t)node * 64 + 4 * sl) = make_float4(vx, vy, vz, vw);
    }
}

// ------------- head: logits = emb @ Wc + bc, softmax, argmax -------------
// one warp per node, 16 nodes per 512-thread block.
__global__ void __launch_bounds__(512) k_head(const float* __restrict__ emb,
                       const float* __restrict__ Wc,
                       const float* __restrict__ bc, float* __restrict__ logits,
                       float* __restrict__ soft, float* __restrict__ hard, int n) {
    __shared__ float sW[64 * OUT_F];
    __shared__ float sb[OUT_F];
    __shared__ float sE[16][64];

    int t = threadIdx.x;
    for (int i = t; i < 64 * OUT_F; i += 512) sW[i] = Wc[i];
    if (t < OUT_F) sb[t] = bc[t];

    int w = t >> 5, lane = t & 31;
    int node = blockIdx.x * 16 + w;
    if (node < n) {
        sE[w][lane]      = emb[(size_t)node * 64 + lane];
        sE[w][lane + 32] = emb[(size_t)node * 64 + lane + 32];
    }
    __syncthreads();
    if (node >= n) return;

    float acc0 = sb[lane];
    float acc1 = (lane < 8) ? sb[lane + 32] : 0.f;
    #pragma unroll 8
    for (int k = 0; k < 64; k++) {
        float e = sE[w][k];
        acc0 += e * sW[k * OUT_F + lane];
        if (lane < 8) acc1 += e * sW[k * OUT_F + lane + 32];
    }

    logits[(size_t)node * OUT_F + lane] = acc0;
    if (lane < 8) logits[(size_t)node * OUT_F + lane + 32] = acc1;

    float m = fmaxf(acc0, (lane < 8) ? acc1 : -FLT_MAX);
    #pragma unroll
    for (int o = 16; o > 0; o >>= 1) m = fmaxf(m, __shfl_xor_sync(0xffffffffu, m, o));
    float e0 = __expf(acc0 - m);
    float e1 = (lane < 8) ? __expf(acc1 - m) : 0.f;
    float s = e0 + e1;
    #pragma unroll
    for (int o = 16; o > 0; o >>= 1) s += __shfl_xor_sync(0xffffffffu, s, o);
    float inv = 1.f / s;
    soft[(size_t)node * OUT_F + lane] = e0 * inv;
    if (lane < 8) soft[(size_t)node * OUT_F + lane + 32] = e1 * inv;

    int cand = 0x7fffffff;
    if (acc0 == m) cand = lane;
    if (lane < 8 && acc1 == m) cand = min(cand, lane + 32);
    #pragma unroll
    for (int o = 16; o > 0; o >>= 1) cand = min(cand, __shfl_xor_sync(0xffffffffu, cand, o));
    if (lane == 0) hard[node] = (float)cand;
}

extern "C" void kernel_launch(void* const* d_in, const int* in_sizes, int n_in,
                              void* d_out, int out_size) {
    const float* x  = (const float*)d_in[0];
    const void*  ei = d_in[1];
    const float* W1 = (const float*)d_in[2];
    const float* b1 = (const float*)d_in[3];
    const float* W2 = (const float*)d_in[4];
    const float* b2 = (const float*)d_in[5];
    const float* Wc = (const float*)d_in[6];
    const float* bc = (const float*)d_in[7];

    const int N = in_sizes[0] / IN_F;
    const int E = in_sizes[1] / 2;

    float* outp   = (float*)d_out;
    float* logits = outp;
    float* emb    = outp + (size_t)N * OUT_F;
    float* soft   = emb  + (size_t)N * HID;
    float* hard   = soft + (size_t)N * OUT_F;

    const int TB = 256;

    k_init<<<(N + TB - 1) / TB, TB>>>((const long long*)ei, N);         // 1
    k_convert<<<(2 * E + TB - 1) / TB, TB>>>(ei, E);                    // 2

    // layer 1
    k_gemm_hs<IN_F><<<(N + 63) / 64, 256>>>(x, W1, g_h1, N);            // 3
    k_scatter<<<(E * 16 + TB - 1) / TB, TB>>>(g_h1, E);                 // 4 <- PROFILED
    k_bias_act<<<(N * 16 + TB - 1) / TB, TB>>>(g_h1, b1, N, 1);         // 5

    // layer 2
    k_gemm_hs<HID><<<(N + 63) / 64, 256>>>(g_h1, W2, emb, N);           // 6
    k_scatter<<<(E * 16 + TB - 1) / TB, TB>>>(emb, E);                  // 7
    k_bias_act<<<(N * 16 + TB - 1) / TB, TB>>>(emb, b2, N, 0);          // 8

    // head
    k_head<<<(N + 15) / 16, 512>>>(emb, Wc, bc, logits, soft, hard, N); // 9
}

// round 17
// speedup vs baseline: 6.5272x; 6.5272x over previous
#include <cuda_runtime.h>
#include <cstdint>
#include <float.h>

#define N_NODES 100000
#define N_EDGES 1200000
#define IN_F 128
#define HID 64
#define OUT_F 40
#define SCAN_B 1024
#define NSCAN ((N_NODES + SCAN_B - 1) / SCAN_B)   // 98 blocks

// ---------------- device scratch (no allocations allowed) ----------------
__device__ int    g_deg[N_NODES];          // in-degree incl. self-loop
__device__ float  g_dinv[N_NODES];
__device__ int    g_rowptr[N_NODES + 1];   // CSR row pointers (real edges only)
__device__ int    g_cur[N_NODES];          // fill cursors
__device__ int    g_csr[N_EDGES];          // src node per CSR slot
__device__ int    g_edge[2 * N_EDGES];     // int32 [src | dst]
__device__ int    g_is64;
__device__ int    g_part[NSCAN];           // per-block partial sums
__device__ float  g_hs[(size_t)N_NODES * HID];   // fp32 prescaled feats (self term)
__device__ short2 g_hq[(size_t)N_NODES * 32];    // int16-quantized rows (128B each)
__device__ float  g_rscale[N_NODES];             // per-row dequant scale (L1-resident)
__device__ float  g_h1[(size_t)N_NODES * HID];   // layer-1 activations

// -------- init: detect edge dtype + deg=1 (self-loop) --------
__global__ void k_init(const long long* __restrict__ ei, int n) {
    int i = blockIdx.x * blockDim.x + threadIdx.x;
    if (i < n) g_deg[i] = 1;
    if (i == 0) {
        int ok = 1;
        #pragma unroll
        for (int j = 0; j < 16; j++) {
            long long v = ei[j];
            if (v < 0 || v >= n) ok = 0;
        }
        g_is64 = ok;
    }
}

// convert to int32 + count in-degree of dst half in one pass
__global__ void k_convert(const void* __restrict__ ei, int e) {
    int i = blockIdx.x * blockDim.x + threadIdx.x;
    if (i < 2 * e) {
        int v = g_is64 ? (int)((const long long*)ei)[i]
                       : ((const int*)ei)[i];
        g_edge[i] = v;
        if (i >= e) atomicAdd(&g_deg[v], 1);
    }
}

// -------- scan level A: per-block partial sums (+ dinv) --------
__global__ void __launch_bounds__(SCAN_B) k_scanA(int n) {
    __shared__ int wsum[32];
    int t = threadIdx.x, lane = t & 31, wid = t >> 5;
    int i = blockIdx.x * SCAN_B + t;
    int d = (i < n) ? g_deg[i] : 1;
    if (i < n) g_dinv[i] = rsqrtf((float)d);
    int v = d - 1;
    int s = v;
    #pragma unroll
    for (int o = 16; o > 0; o >>= 1) s += __shfl_xor_sync(0xffffffffu, s, o);
    if (lane == 0) wsum[wid] = s;
    __syncthreads();
    if (wid == 0) {
        int ws = wsum[lane];
        #pragma unroll
        for (int o = 16; o > 0; o >>= 1) ws += __shfl_xor_sync(0xffffffffu, ws, o);
        if (lane == 0) g_part[blockIdx.x] = ws;
    }
}

// -------- scan B+C fused: prefix of partials + local scan -> rowptr, cur ----
__global__ void __launch_bounds__(SCAN_B) k_scanC(int n) {
    __shared__ int wsum[32];
    __shared__ int s_off;
    int t = threadIdx.x, lane = t & 31, wid = t >> 5;

    if (wid == 0) {
        int p = 0;
        for (int i = lane; i < (int)blockIdx.x; i += 32) p += g_part[i];
        #pragma unroll
        for (int o = 16; o > 0; o >>= 1) p += __shfl_xor_sync(0xffffffffu, p, o);
        if (lane == 0) {
            s_off = p;
            if (blockIdx.x == NSCAN - 1)
                g_rowptr[n] = p + g_part[NSCAN - 1];  // total real edges
        }
    }

    int i = blockIdx.x * SCAN_B + t;
    int v = (i < n) ? (g_deg[i] - 1) : 0;
    int incl = v;
    #pragma unroll
    for (int o = 1; o < 32; o <<= 1) {
        int u = __shfl_up_sync(0xffffffffu, incl, o);
        if (lane >= o) incl += u;
    }
    if (lane == 31) wsum[wid] = incl;
    __syncthreads();
    if (wid == 0) {
        int ws = wsum[lane];
        int wi = ws;
        #pragma unroll
        for (int o = 1; o < 32; o <<= 1) {
            int u = __shfl_up_sync(0xffffffffu, wi, o);
            if (lane >= o) wi += u;
        }
        wsum[lane] = wi - ws;
    }
    __syncthreads();
    if (i < n) {
        int excl = s_off + wsum[wid] + (incl - v);
        g_rowptr[i] = excl;
        g_cur[i] = excl;
    }
}

__global__ void k_fill(int e) {
    int i = blockIdx.x * blockDim.x + threadIdx.x;
    if (i < e) {
        int s = g_edge[i];
        int d = g_edge[e + i];
        int pos = atomicAdd(&g_cur[d], 1);
        g_csr[pos] = s;
    }
}

// --- dense GEMM: hs = (A @ W) * dinv[row]; dual-write fp32 + int16-quant ---
// rowmax reduced across the 16 lanes owning each row (shfl_xor 1,2,4,8).
template <int K>
__global__ void k_gemm_hs(const float* __restrict__ A, const float* __restrict__ W, int n) {
    __shared__ __align__(16) float sW[64 * 64];
    __shared__ float sA[64 * 65];

    const int t = threadIdx.x;           // 256 threads
    const int row0 = blockIdx.x * 64;
    const int ty = t >> 4, tx = t & 15;  // 16x16 thread tile
    const int r0 = ty * 4, c0 = tx * 4;

    float acc[4][4] = {};

    for (int k0 = 0; k0 < K; k0 += 64) {
        __syncthreads();
        for (int i = t; i < 64 * 64 / 4; i += 256)
            ((float4*)sW)[i] = ((const float4*)(W + (size_t)k0 * 64))[i];
        for (int i = t; i < 64 * 16; i += 256) {
            int r = i >> 4;
            int kc = (i & 15) * 4;
            float4 v = make_float4(0.f, 0.f, 0.f, 0.f);
            if (row0 + r < n)
                v = *(const float4*)(A + (size_t)(row0 + r) * K + k0 + kc);
            float* d = &sA[r * 65 + kc];
            d[0] = v.x; d[1] = v.y; d[2] = v.z; d[3] = v.w;
        }
        __syncthreads();

        #pragma unroll 8
        for (int kk = 0; kk < 64; kk++) {
            float4 w4 = *(float4*)&sW[kk * 64 + c0];
            #pragma unroll
            for (int j = 0; j < 4; j++) {
                float a = sA[(r0 + j) * 65 + kk];
                acc[j][0] += a * w4.x;
                acc[j][1] += a * w4.y;
                acc[j][2] += a * w4.z;
                acc[j][3] += a * w4.w;
            }
        }
    }

    #pragma unroll
    for (int j = 0; j < 4; j++) {
        int r = row0 + r0 + j;
        float dv = (r < n) ? g_dinv[r] : 0.f;
        float4 v = make_float4(acc[j][0] * dv, acc[j][1] * dv,
                               acc[j][2] * dv, acc[j][3] * dv);
        // rowmax across the 16 lanes owning this row (lane-group is 16-aligned)
        float m = fmaxf(fmaxf(fabsf(v.x), fabsf(v.y)),
                        fmaxf(fabsf(v.z), fabsf(v.w)));
        #pragma unroll
        for (int o = 8; o > 0; o >>= 1)
            m = fmaxf(m, __shfl_xor_sync(0xffffffffu, m, o));
        float inv_s = 32767.f / fmaxf(m, 1e-30f);
        if (r < n) {
            *(float4*)&g_hs[(size_t)r * 64 + c0] = v;
            if (tx == 0) g_rscale[r] = fmaxf(m, 1e-30f) * (1.f / 32767.f);
            short2 q0 = make_short2((short)__float2int_rn(v.x * inv_s),
                                    (short)__float2int_rn(v.y * inv_s));
            short2 q1 = make_short2((short)__float2int_rn(v.z * inv_s),
                                    (short)__float2int_rn(v.w * inv_s));
            g_hq[(size_t)r * 32 + (c0 >> 1)]     = q0;
            g_hq[(size_t)r * 32 + (c0 >> 1) + 1] = q1;
        }
    }
}

// agg: out[v] = act(dinv[v]*(hs[v] + sum q[src]*scale[src]) + b)
// one warp per node; lane owns 2 feats (one short2 = 4B; warp = 128B = 1 line).
// Per-row scales come from the 400KB L1-resident g_rscale. Batch 8 -> 4 -> 1.
__global__ void k_agg(const float* __restrict__ b, float* __restrict__ out,
                      int n, int do_relu) {
    int gw = (blockIdx.x * blockDim.x + threadIdx.x) >> 5;
    int lane = threadIdx.x & 31;
    if (gw >= n) return;

    int beg = g_rowptr[gw], end = g_rowptr[gw + 1];
    float2 selfv = *(const float2*)(g_hs + (size_t)gw * 64 + 2 * lane);
    float ax = selfv.x, ay = selfv.y;
    float bx = 0.f, by = 0.f;

    int j = beg;
    for (; j + 8 <= end; j += 8) {
        int s0 = g_csr[j];
        int s1 = g_csr[j + 1];
        int s2 = g_csr[j + 2];
        int s3 = g_csr[j + 3];
        int s4 = g_csr[j + 4];
        int s5 = g_csr[j + 5];
        int s6 = g_csr[j + 6];
        int s7 = g_csr[j + 7];
        float c0 = g_rscale[s0];
        float c1 = g_rscale[s1];
        float c2 = g_rscale[s2];
        float c3 = g_rscale[s3];
        float c4 = g_rscale[s4];
        float c5 = g_rscale[s5];
        float c6 = g_rscale[s6];
        float c7 = g_rscale[s7];
        short2 q0 = g_hq[(size_t)s0 * 32 + lane];
        short2 q1 = g_hq[(size_t)s1 * 32 + lane];
        short2 q2 = g_hq[(size_t)s2 * 32 + lane];
        short2 q3 = g_hq[(size_t)s3 * 32 + lane];
        short2 q4 = g_hq[(size_t)s4 * 32 + lane];
        short2 q5 = g_hq[(size_t)s5 * 32 + lane];
        short2 q6 = g_hq[(size_t)s6 * 32 + lane];
        short2 q7 = g_hq[(size_t)s7 * 32 + lane];
        ax += c0 * (float)q0.x + c1 * (float)q1.x + c2 * (float)q2.x + c3 * (float)q3.x;
        bx += c4 * (float)q4.x + c5 * (float)q5.x + c6 * (float)q6.x + c7 * (float)q7.x;
        ay += c0 * (float)q0.y + c1 * (float)q1.y + c2 * (float)q2.y + c3 * (float)q3.y;
        by += c4 * (float)q4.y + c5 * (float)q5.y + c6 * (float)q6.y + c7 * (float)q7.y;
    }
    if (j + 4 <= end) {
        int s0 = g_csr[j];
        int s1 = g_csr[j + 1];
        int s2 = g_csr[j + 2];
        int s3 = g_csr[j + 3];
        float c0 = g_rscale[s0];
        float c1 = g_rscale[s1];
        float c2 = g_rscale[s2];
        float c3 = g_rscale[s3];
        short2 q0 = g_hq[(size_t)s0 * 32 + lane];
        short2 q1 = g_hq[(size_t)s1 * 32 + lane];
        short2 q2 = g_hq[(size_t)s2 * 32 + lane];
        short2 q3 = g_hq[(size_t)s3 * 32 + lane];
        ax += c0 * (float)q0.x + c1 * (float)q1.x + c2 * (float)q2.x + c3 * (float)q3.x;
        ay += c0 * (float)q0.y + c1 * (float)q1.y + c2 * (float)q2.y + c3 * (float)q3.y;
        j += 4;
    }
    for (; j < end; j++) {
        int s = g_csr[j];
        float c = g_rscale[s];
        short2 q = g_hq[(size_t)s * 32 + lane];
        bx += c * (float)q.x;
        by += c * (float)q.y;
    }
    ax += bx;
    ay += by;

    float dv = g_dinv[gw];
    float vx = ax * dv + b[2 * lane];
    float vy = ay * dv + b[2 * lane + 1];
    if (do_relu) { vx = fmaxf(vx, 0.f); vy = fmaxf(vy, 0.f); }
    *(float2*)(out + (size_t)gw * 64 + 2 * lane) = make_float2(vx, vy);
}

// ------------- head: logits = emb @ Wc + bc, softmax, argmax -------------
// one warp per node, 16 nodes per 512-thread block.
__global__ void __launch_bounds__(512) k_head(const float* __restrict__ emb,
                       const float* __restrict__ Wc,
                       const float* __restrict__ bc, float* __restrict__ logits,
                       float* __restrict__ soft, float* __restrict__ hard, int n) {
    __shared__ float sW[64 * OUT_F];
    __shared__ float sb[OUT_F];
    __shared__ float sE[16][64];

    int t = threadIdx.x;
    for (int i = t; i < 64 * OUT_F; i += 512) sW[i] = Wc[i];
    if (t < OUT_F) sb[t] = bc[t];

    int w = t >> 5, lane = t & 31;
    int node = blockIdx.x * 16 + w;
    if (node < n) {
        sE[w][lane]      = emb[(size_t)node * 64 + lane];
        sE[w][lane + 32] = emb[(size_t)node * 64 + lane + 32];
    }
    __syncthreads();
    if (node >= n) return;

    float acc0 = sb[lane];
    float acc1 = (lane < 8) ? sb[lane + 32] : 0.f;
    #pragma unroll 8
    for (int k = 0; k < 64; k++) {
        float e = sE[w][k];
        acc0 += e * sW[k * OUT_F + lane];
        if (lane < 8) acc1 += e * sW[k * OUT_F + lane + 32];
    }

    logits[(size_t)node * OUT_F + lane] = acc0;
    if (lane < 8) logits[(size_t)node * OUT_F + lane + 32] = acc1;

    float m = fmaxf(acc0, (lane < 8) ? acc1 : -FLT_MAX);
    #pragma unroll
    for (int o = 16; o > 0; o >>= 1) m = fmaxf(m, __shfl_xor_sync(0xffffffffu, m, o));
    float e0 = __expf(acc0 - m);
    float e1 = (lane < 8) ? __expf(acc1 - m) : 0.f;
    float s = e0 + e1;
    #pragma unroll
    for (int o = 16; o > 0; o >>= 1) s += __shfl_xor_sync(0xffffffffu, s, o);
    float inv = 1.f / s;
    soft[(size_t)node * OUT_F + lane] = e0 * inv;
    if (lane < 8) soft[(size_t)node * OUT_F + lane + 32] = e1 * inv;

    int cand = 0x7fffffff;
    if (acc0 == m) cand = lane;
    if (lane < 8 && acc1 == m) cand = min(cand, lane + 32);
    #pragma unroll
    for (int o = 16; o > 0; o >>= 1) cand = min(cand, __shfl_xor_sync(0xffffffffu, cand, o));
    if (lane == 0) hard[node] = (float)cand;
}

extern "C" void kernel_launch(void* const* d_in, const int* in_sizes, int n_in,
                              void* d_out, int out_size) {
    const float* x  = (const float*)d_in[0];
    const void*  ei = d_in[1];
    const float* W1 = (const float*)d_in[2];
    const float* b1 = (const float*)d_in[3];
    const float* W2 = (const float*)d_in[4];
    const float* b2 = (const float*)d_in[5];
    const float* Wc = (const float*)d_in[6];
    const float* bc = (const float*)d_in[7];

    const int N = in_sizes[0] / IN_F;
    const int E = in_sizes[1] / 2;

    float* outp   = (float*)d_out;
    float* logits = outp;
    float* emb    = outp + (size_t)N * OUT_F;
    float* soft   = emb  + (size_t)N * HID;
    float* hard   = soft + (size_t)N * OUT_F;

    const int TB = 256;

    k_init<<<(N + TB - 1) / TB, TB>>>((const long long*)ei, N);     // 1
    k_convert<<<(2 * E + TB - 1) / TB, TB>>>(ei, E);                // 2
    k_scanA<<<NSCAN, SCAN_B>>>(N);                                  // 3
    k_gemm_hs<IN_F><<<(N + 63) / 64, 256>>>(x, W1, N);              // 4  <- profiled
    k_scanC<<<NSCAN, SCAN_B>>>(N);                                  // 5
    k_fill<<<(E + TB - 1) / TB, TB>>>(E);                           // 6

    // layer 1 aggregation: g_h1 = relu(agg + b1)
    k_agg<<<((N * 32) + TB - 1) / TB, TB>>>(b1, g_h1, N, 1);        // 7

    // layer 2
    k_gemm_hs<HID><<<(N + 63) / 64, 256>>>(g_h1, W2, N);            // 8
    k_agg<<<((N * 32) + TB - 1) / TB, TB>>>(b2, emb, N, 0);         // 9

    // head
    k_head<<<(N + 15) / 16, 512>>>(emb, Wc, bc, logits, soft, hard, N);  // 10
}